// round 1
// baseline (speedup 1.0000x reference)
#include <cuda_runtime.h>

// Problem constants (fixed by setup_inputs):
//   M = 320000 voxels, D = 256, B = 4, WX = WY = 128, Mp = 32000 unique
//   key = ((b*Z_CAP + z)*WY + y)*WX + x, Z_CAP = 1, z = 0
//   key == flat2batch_inds == b*16384 + y*128 + x  (key space = 65536)
#define NK     65536
#define WXC    128
#define WYC    128
#define DC     256
#define MAXM   320000

// Output layout: tuple flattened to float32 in return order
//   [0)                feat_batch   (4*16384*256)
//   [16777216)         pos_emb      (4*16384*256)
//   [33554432)         key_padding  (65536)
//   [33619968)         flat2batch   (32000)
//   [33651968)         coords       (32000*4)
#define O_POS  16777216
#define O_PAD  33554432
#define O_IND  33619968
#define O_CRD  33651968

__device__ int g_counts[NK];
__device__ int g_offsets[NK];
__device__ int g_cursor[NK];
__device__ int g_rank[NK];
__device__ int g_incl_c[NK];
__device__ int g_incl_o[NK];
__device__ int g_bexc[64];
__device__ int g_bexo[64];
__device__ int g_sorted[MAXM];

__device__ __forceinline__ int vkey(int4 w) {
    // w = (b, z, y, x); Z_CAP = 1
    return ((w.x + w.y) * WYC + w.z) * WXC + w.w;
}

__global__ void k_zero() {
    int i = blockIdx.x * blockDim.x + threadIdx.x;
    if (i < NK) g_counts[i] = 0;
}

__global__ void k_hist(const int4* __restrict__ win, int M) {
    int i = blockIdx.x * blockDim.x + threadIdx.x;
    if (i < M) atomicAdd(&g_counts[vkey(win[i])], 1);
}

// Two-level scan over 65536 entries, scanning (counts, occupancy) jointly.
__global__ void k_scan1() {
    __shared__ int sa[1024], sb[1024];
    int b = blockIdx.x, t = threadIdx.x;
    int i = b * 1024 + t;
    int c = g_counts[i];
    sa[t] = c; sb[t] = (c > 0);
    __syncthreads();
    for (int d = 1; d < 1024; d <<= 1) {
        int va = (t >= d) ? sa[t - d] : 0;
        int vb = (t >= d) ? sb[t - d] : 0;
        __syncthreads();
        sa[t] += va; sb[t] += vb;
        __syncthreads();
    }
    g_incl_c[i] = sa[t];
    g_incl_o[i] = sb[t];
    if (t == 1023) { g_bexc[b] = sa[t]; g_bexo[b] = sb[t]; }
}

__global__ void k_scan2() {
    if (threadIdx.x == 0) {
        int ec = 0, eo = 0;
        for (int b = 0; b < 64; b++) {
            int tc = g_bexc[b], to = g_bexo[b];
            g_bexc[b] = ec; g_bexo[b] = eo;
            ec += tc; eo += to;
        }
    }
}

__global__ void k_scan3() {
    int b = blockIdx.x, t = threadIdx.x;
    int i = b * 1024 + t;
    int c = g_counts[i];
    int excl = g_bexc[b] + g_incl_c[i] - c;
    g_offsets[i] = excl;
    g_cursor[i]  = excl;
    g_rank[i]    = g_bexo[b] + g_incl_o[i] - (c > 0);
}

__global__ void k_scatter(const int4* __restrict__ win, int M) {
    int i = blockIdx.x * blockDim.x + threadIdx.x;
    if (i < M) {
        int p = atomicAdd(&g_cursor[vkey(win[i])], 1);
        g_sorted[p] = i;
    }
}

// One block per key-slot k (== output slot == flat2batch index).
__global__ void __launch_bounds__(256) k_final(const float* __restrict__ vf,
                                               float* __restrict__ out) {
    int k = blockIdx.x;
    int t = threadIdx.x;
    float* out_feat = out;
    float* out_pos  = out + O_POS;
    float* out_pad  = out + O_PAD;
    float* out_ind  = out + O_IND;
    float* out_crd  = out + O_CRD;

    int cnt = g_counts[k];
    size_t ko = (size_t)k * DC + t;
    if (cnt == 0) {
        out_feat[ko] = 0.0f;
        out_pos[ko]  = 0.0f;
        if (t == 0) out_pad[k] = 1.0f;
        return;
    }

    int off = g_offsets[k];
    __shared__ int sidx[256];
    float acc = 0.0f;
    for (int base = 0; base < cnt; base += 256) {
        int n = min(256, cnt - base);
        __syncthreads();
        if (t < n) sidx[t] = g_sorted[off + base + t];
        __syncthreads();
        int j = 0;
        for (; j + 4 <= n; j += 4) {
            // 4 independent loads -> MLP=4 to hide DRAM latency
            float a0 = vf[(size_t)sidx[j + 0] * DC + t];
            float a1 = vf[(size_t)sidx[j + 1] * DC + t];
            float a2 = vf[(size_t)sidx[j + 2] * DC + t];
            float a3 = vf[(size_t)sidx[j + 3] * DC + t];
            acc += (a0 + a1) + (a2 + a3);
        }
        for (; j < n; j++) acc += vf[(size_t)sidx[j] * DC + t];
    }
    out_feat[ko] = acc * (1.0f / (float)cnt);

    // positional embedding: first 128 dims from x, last 128 from y
    int xu = k & 127;
    int yu = (k >> 7) & 127;
    int bu = k >> 14;
    int jj = (t < 128) ? t : (t - 128);
    float c = ((t < 128) ? (float)xu : (float)yu) - 64.0f;  // WX/2 = WY/2 = 64
    float expo = (float)(jj & ~1) * (1.0f / 128.0f);
    float invf = exp2f(expo * 13.287712379549449f);         // 10000^expo
    float e = c / invf;
    out_pos[ko] = (jj & 1) ? cosf(e) : sinf(e);

    if (t == 0) {
        out_pad[k] = 0.0f;
        int r = g_rank[k];
        out_ind[r] = (float)k;
        out_crd[(size_t)r * 4 + 0] = (float)bu;
        out_crd[(size_t)r * 4 + 1] = 0.0f;
        out_crd[(size_t)r * 4 + 2] = (float)yu;
        out_crd[(size_t)r * 4 + 3] = (float)xu;
    }
}

extern "C" void kernel_launch(void* const* d_in, const int* in_sizes, int n_in,
                              void* d_out, int out_size) {
    const float* vf  = (const float*)d_in[0];
    const int4*  win = (const int4*)d_in[1];
    int M = in_sizes[1] / 4;
    float* out = (float*)d_out;

    k_zero   <<<NK / 256, 256>>>();
    k_hist   <<<(M + 255) / 256, 256>>>(win, M);
    k_scan1  <<<64, 1024>>>();
    k_scan2  <<<1, 32>>>();
    k_scan3  <<<64, 1024>>>();
    k_scatter<<<(M + 255) / 256, 256>>>(win, M);
    k_final  <<<NK, 256>>>(vf, out);
}